// round 7
// baseline (speedup 1.0000x reference)
#include <cuda_runtime.h>
#include <cuda_bf16.h>
#include <cstdint>
#include <cstddef>

#define NN 100000
#define RR 6
#define EE 400000
#define FF 128
#define KT 768          // RR*FF
#define RN 600000       // RR*NN
#define RE 2400000      // RR*EE
#define NB 586          // ceil(RN/1024)

// ---------------- scratch (device globals) ----------------
__device__ int   g_deg_out[RN];
__device__ int   g_deg_in[RN];
__device__ float g_norm_src[RN];
__device__ float g_norm_dst[RN];
__device__ int   g_offs[RN + 1];
__device__ int   g_bsums[NB];
__device__ int   g_boffs[NB];
__device__ int   g_cursor[RN];
__device__ int   g_csrc[RE];
__device__ float g_cw[RE];
__device__ float g_c[RN];
__device__ float g_bsum1[FF];
__device__ float g_Y[(size_t)NN * KT];   // aggregated features [N, 768]
__device__ float g_h[(size_t)NN * FF];   // layer-1 output
__device__ float g_s[RR * FF];           // layer-2 pooled vectors

// ---------------- kernels ----------------
__global__ void k_deg(const int* __restrict__ src, const int* __restrict__ dst) {
    int i = blockIdx.x * blockDim.x + threadIdx.x;
    if (i >= RE) return;
    int r = i / EE;
    atomicAdd(&g_deg_out[r * NN + src[i]], 1);
    atomicAdd(&g_deg_in [r * NN + dst[i]], 1);
}

__global__ void k_norm() {
    int i = blockIdx.x * blockDim.x + threadIdx.x;
    if (i >= RN) return;
    int d0 = g_deg_out[i], d1 = g_deg_in[i];
    g_norm_src[i] = d0 > 0 ? rsqrtf((float)d0) : 0.f;
    g_norm_dst[i] = d1 > 0 ? rsqrtf((float)d1) : 0.f;
}

__global__ void k_scan1() {
    __shared__ int s[1024];
    int t = threadIdx.x, i = blockIdx.x * 1024 + t;
    int v = (i < RN) ? g_deg_in[i] : 0;
    s[t] = v; __syncthreads();
    for (int d = 1; d < 1024; d <<= 1) {
        int u = (t >= d) ? s[t - d] : 0;
        __syncthreads();
        s[t] += u; __syncthreads();
    }
    if (i < RN) g_offs[i] = s[t] - v;          // exclusive within block
    if (t == 1023) g_bsums[blockIdx.x] = s[1023];
}

__global__ void k_scan2() {
    __shared__ int s[1024];
    int t = threadIdx.x;
    int v = (t < NB) ? g_bsums[t] : 0;
    s[t] = v; __syncthreads();
    for (int d = 1; d < 1024; d <<= 1) {
        int u = (t >= d) ? s[t - d] : 0;
        __syncthreads();
        s[t] += u; __syncthreads();
    }
    if (t < NB) g_boffs[t] = s[t] - v;
}

__global__ void k_scan3() {
    int t = threadIdx.x, i = blockIdx.x * 1024 + t;
    if (i < RN) g_offs[i] += g_boffs[blockIdx.x];
    if (i == 0) g_offs[RN] = RE;
}

__global__ void k_fill(const int* __restrict__ src, const int* __restrict__ dst) {
    int i = blockIdx.x * blockDim.x + threadIdx.x;
    if (i >= RE) return;
    int r = i / EE, s = src[i], d = dst[i];
    int row = r * NN + d;
    int pos  = atomicAdd(&g_cursor[row], 1);
    int slot = g_offs[row] + pos;
    g_csrc[slot] = s;
    g_cw[slot]   = g_norm_src[r * NN + s];
    // layer-2 coefficient: c_r[src] += norm_dst_r[dst]
    atomicAdd(&g_c[r * NN + s], g_norm_dst[row]);
}

// warp per (relation, dst-node) row: Y[n, r*128+f] = norm_dst * sum_e w_e * x[src_e][f]
__global__ void k_agg(const float* __restrict__ x) {
    int w = (blockIdx.x * blockDim.x + threadIdx.x) >> 5;
    int lane = threadIdx.x & 31;
    if (w >= RN) return;
    int beg = g_offs[w], end = g_offs[w + 1];
    const float4* x4 = (const float4*)x;
    float4 acc = make_float4(0.f, 0.f, 0.f, 0.f);
    for (int j = beg; j < end; j++) {
        int   s  = g_csrc[j];
        float wt = g_cw[j];
        float4 xv = x4[(size_t)s * 32 + lane];
        acc.x += wt * xv.x; acc.y += wt * xv.y;
        acc.z += wt * xv.z; acc.w += wt * xv.w;
    }
    float nd = g_norm_dst[w];
    int r = w / NN, n = w - r * NN;
    float4 o = make_float4(acc.x * nd, acc.y * nd, acc.z * nd, acc.w * nd);
    ((float4*)g_Y)[(size_t)n * 192 + r * 32 + lane] = o;
}

__global__ void k_bsum1(const float* __restrict__ b1) {
    int t = threadIdx.x;
    float a = 0.f;
#pragma unroll
    for (int r = 0; r < RR; r++) a += b1[r * FF + t];
    g_bsum1[t] = a;
}

// h = relu(Y[100k,768] @ W1[768,128] + bsum1), 128x128 block tile, 8x8 per thread
__global__ void __launch_bounds__(256, 2) k_gemm(const float* __restrict__ B) {
    __shared__ float As[8][128];
    __shared__ float Bs[8][128];
    int tid = threadIdx.x;
    int tx = tid & 15, ty = tid >> 4;
    int m0 = blockIdx.x * 128;
    int aRow = tid >> 1, aCol = (tid & 1) * 4;
    int bRow = tid >> 5, bCol = (tid & 31) * 4;
    int gRow = m0 + aRow;
    bool aOK = gRow < NN;
    const float* A = g_Y;

    float acc[8][8];
#pragma unroll
    for (int i = 0; i < 8; i++)
#pragma unroll
        for (int j = 0; j < 8; j++) acc[i][j] = 0.f;

    for (int k0 = 0; k0 < KT; k0 += 8) {
        float4 av = aOK ? *(const float4*)&A[(size_t)gRow * KT + k0 + aCol]
                        : make_float4(0.f, 0.f, 0.f, 0.f);
        float4 bv = *(const float4*)&B[(k0 + bRow) * FF + bCol];
        As[aCol + 0][aRow] = av.x; As[aCol + 1][aRow] = av.y;
        As[aCol + 2][aRow] = av.z; As[aCol + 3][aRow] = av.w;
        *(float4*)&Bs[bRow][bCol] = bv;
        __syncthreads();
#pragma unroll
        for (int k = 0; k < 8; k++) {
            float af[8], bf[8];
#pragma unroll
            for (int i = 0; i < 8; i++) af[i] = As[k][ty * 8 + i];
#pragma unroll
            for (int j = 0; j < 8; j++) bf[j] = Bs[k][tx * 8 + j];
#pragma unroll
            for (int i = 0; i < 8; i++)
#pragma unroll
                for (int j = 0; j < 8; j++) acc[i][j] += af[i] * bf[j];
        }
        __syncthreads();
    }

    float bb[8];
#pragma unroll
    for (int j = 0; j < 8; j++) bb[j] = g_bsum1[tx * 8 + j];
#pragma unroll
    for (int i = 0; i < 8; i++) {
        int row = m0 + ty * 8 + i;
        if (row < NN) {
#pragma unroll
            for (int j = 0; j < 8; j++)
                g_h[(size_t)row * FF + tx * 8 + j] = fmaxf(acc[i][j] + bb[j], 0.f);
        }
    }
}

// s[r][f] = sum_n (norm_src_r[n]*c_r[n]) * h[n][f]
__global__ void k_reduce() {
    __shared__ float wc[RR][128];
    int t = threadIdx.x;                 // 128 threads = one column each
    int base = blockIdx.x * 128;
    int n = base + t;
#pragma unroll
    for (int r = 0; r < RR; r++)
        wc[r][t] = (n < NN) ? g_norm_src[r * NN + n] * g_c[r * NN + n] : 0.f;
    __syncthreads();
    float acc[RR] = {0.f, 0.f, 0.f, 0.f, 0.f, 0.f};
    int lim = min(128, NN - base);
    for (int ni = 0; ni < lim; ni++) {
        float hv = g_h[(size_t)(base + ni) * FF + t];
#pragma unroll
        for (int r = 0; r < RR; r++) acc[r] += wc[r][ni] * hv;
    }
#pragma unroll
    for (int r = 0; r < RR; r++) atomicAdd(&g_s[r * FF + t], acc[r]);
}

// g[f] = (1/N)*sum_{r,k} s[r][k]*W2[r][k][f] + sum_r b2[r][f];  out = g@Wc + bc
__global__ void k_final(const float* __restrict__ W2, const float* __restrict__ b2,
                        const float* __restrict__ Wc, const float* __restrict__ bc,
                        float* __restrict__ out) {
    __shared__ float g[FF];
    int f = threadIdx.x;
    float acc = 0.f;
    for (int rk = 0; rk < RR * FF; rk++)
        acc += g_s[rk] * W2[(size_t)rk * FF + f];
    float gb = 0.f;
#pragma unroll
    for (int r = 0; r < RR; r++) gb += b2[r * FF + f];
    g[f] = acc * (1.f / NN) + gb;
    __syncthreads();
    if (f < 2) {
        float o = bc[f];
        for (int k = 0; k < FF; k++) o += g[k] * Wc[k * 2 + f];
        out[f] = o;
    }
}

// ---------------- launch ----------------
extern "C" void kernel_launch(void* const* d_in, const int* in_sizes, int n_in,
                              void* d_out, int out_size) {
    const float* x    = (const float*)d_in[0];
    const int*   esrc = (const int*)  d_in[1];
    const int*   edst = (const int*)  d_in[2];
    const float* W1   = (const float*)d_in[3];
    const float* b1   = (const float*)d_in[4];
    const float* W2   = (const float*)d_in[5];
    const float* b2   = (const float*)d_in[6];
    const float* Wc   = (const float*)d_in[7];
    const float* bc   = (const float*)d_in[8];
    float* out = (float*)d_out;

    void *p_do, *p_di, *p_cur, *p_c, *p_s;
    cudaGetSymbolAddress(&p_do,  g_deg_out);
    cudaGetSymbolAddress(&p_di,  g_deg_in);
    cudaGetSymbolAddress(&p_cur, g_cursor);
    cudaGetSymbolAddress(&p_c,   g_c);
    cudaGetSymbolAddress(&p_s,   g_s);
    cudaMemsetAsync(p_do,  0, (size_t)RN * 4, 0);
    cudaMemsetAsync(p_di,  0, (size_t)RN * 4, 0);
    cudaMemsetAsync(p_cur, 0, (size_t)RN * 4, 0);
    cudaMemsetAsync(p_c,   0, (size_t)RN * 4, 0);
    cudaMemsetAsync(p_s,   0, (size_t)RR * FF * 4, 0);

    k_deg  <<<(RE + 255) / 256, 256>>>(esrc, edst);
    k_norm <<<(RN + 255) / 256, 256>>>();
    k_scan1<<<NB, 1024>>>();
    k_scan2<<<1, 1024>>>();
    k_scan3<<<NB, 1024>>>();
    k_fill <<<(RE + 255) / 256, 256>>>(esrc, edst);
    k_agg  <<<RN / 8, 256>>>(x);              // 8 warps/block, warp per row
    k_bsum1<<<1, FF>>>(b1);
    k_gemm <<<(NN + 127) / 128, 256>>>(W1);
    k_reduce<<<(NN + 127) / 128, 128>>>();
    k_final<<<1, FF>>>(W2, b2, Wc, bc, out);
}

// round 9
// speedup vs baseline: 1.4210x; 1.4210x over previous
#include <cuda_runtime.h>
#include <cuda_bf16.h>
#include <cstdint>
#include <cstddef>

#define NN 100000
#define RR 6
#define EE 400000
#define FF 128
#define KT 768          // RR*FF
#define RN 600000       // RR*NN
#define RE 2400000      // RR*EE
#define NB 586          // ceil(RN/1024)
#define MPAD 100096     // 782*128 (padded M so GEMM loads need no guard)

// ---------------- scratch (device globals; zero-initialized at load) --------
__device__ int   g_deg_out[RN];
__device__ int   g_deg_in[RN];
__device__ float g_norm_src[RN];
__device__ float g_norm_dst[RN];
__device__ int   g_offs[RN + 1];
__device__ int   g_bsums[NB];
__device__ int   g_boffs[NB];
__device__ int   g_cursor[RN];
__device__ int   g_csrc[RE];
__device__ float g_cw[RE];
__device__ float g_c[RN];
__device__ float g_bsum1[FF];
__device__ __nv_bfloat16 g_Yh[(size_t)MPAD * KT];  // aggregated features, bf16 hi
__device__ __nv_bfloat16 g_Yl[(size_t)MPAD * KT];  // bf16 residual
__device__ __nv_bfloat16 g_Bh[KT * FF];            // W1 split hi
__device__ __nv_bfloat16 g_Bl[KT * FF];            // W1 split lo
__device__ float g_h[(size_t)NN * FF];             // layer-1 output (post-relu)
__device__ float g_s[RR * FF];                     // layer-2 pooled vectors

// ---------------- helpers ----------------------------------------------------
__device__ __forceinline__ uint32_t smem_u32(const void* p) {
    return (uint32_t)__cvta_generic_to_shared(p);
}
__device__ __forceinline__ void ldmx4(uint32_t* r, uint32_t addr) {
    asm volatile("ldmatrix.sync.aligned.m8n8.x4.shared.b16 {%0,%1,%2,%3}, [%4];"
        : "=r"(r[0]), "=r"(r[1]), "=r"(r[2]), "=r"(r[3]) : "r"(addr));
}
__device__ __forceinline__ void ldmx4t(uint32_t* r, uint32_t addr) {
    asm volatile("ldmatrix.sync.aligned.m8n8.x4.trans.shared.b16 {%0,%1,%2,%3}, [%4];"
        : "=r"(r[0]), "=r"(r[1]), "=r"(r[2]), "=r"(r[3]) : "r"(addr));
}
__device__ __forceinline__ void mma16816(float* d, const uint32_t* a, const uint32_t* b) {
    asm volatile(
        "mma.sync.aligned.m16n8k16.row.col.f32.bf16.bf16.f32 "
        "{%0,%1,%2,%3}, {%4,%5,%6,%7}, {%8,%9}, {%0,%1,%2,%3};"
        : "+f"(d[0]), "+f"(d[1]), "+f"(d[2]), "+f"(d[3])
        : "r"(a[0]), "r"(a[1]), "r"(a[2]), "r"(a[3]), "r"(b[0]), "r"(b[1]));
}
__device__ __forceinline__ void bfsplit(float v, __nv_bfloat16& h, __nv_bfloat16& l) {
    h = __float2bfloat16_rn(v);
    l = __float2bfloat16_rn(v - __bfloat162float(h));
}

// ---------------- graph-prep kernels (unchanged from passing R7) -------------
__global__ void k_deg(const int* __restrict__ src, const int* __restrict__ dst) {
    int i = blockIdx.x * blockDim.x + threadIdx.x;
    if (i >= RE) return;
    int r = i / EE;
    atomicAdd(&g_deg_out[r * NN + src[i]], 1);
    atomicAdd(&g_deg_in [r * NN + dst[i]], 1);
}

__global__ void k_norm() {
    int i = blockIdx.x * blockDim.x + threadIdx.x;
    if (i >= RN) return;
    int d0 = g_deg_out[i], d1 = g_deg_in[i];
    g_norm_src[i] = d0 > 0 ? rsqrtf((float)d0) : 0.f;
    g_norm_dst[i] = d1 > 0 ? rsqrtf((float)d1) : 0.f;
}

__global__ void k_scan1() {
    __shared__ int s[1024];
    int t = threadIdx.x, i = blockIdx.x * 1024 + t;
    int v = (i < RN) ? g_deg_in[i] : 0;
    s[t] = v; __syncthreads();
    for (int d = 1; d < 1024; d <<= 1) {
        int u = (t >= d) ? s[t - d] : 0;
        __syncthreads();
        s[t] += u; __syncthreads();
    }
    if (i < RN) g_offs[i] = s[t] - v;
    if (t == 1023) g_bsums[blockIdx.x] = s[1023];
}

__global__ void k_scan2() {
    __shared__ int s[1024];
    int t = threadIdx.x;
    int v = (t < NB) ? g_bsums[t] : 0;
    s[t] = v; __syncthreads();
    for (int d = 1; d < 1024; d <<= 1) {
        int u = (t >= d) ? s[t - d] : 0;
        __syncthreads();
        s[t] += u; __syncthreads();
    }
    if (t < NB) g_boffs[t] = s[t] - v;
}

__global__ void k_scan3() {
    int t = threadIdx.x, i = blockIdx.x * 1024 + t;
    if (i < RN) g_offs[i] += g_boffs[blockIdx.x];
    if (i == 0) g_offs[RN] = RE;
}

__global__ void k_fill(const int* __restrict__ src, const int* __restrict__ dst) {
    int i = blockIdx.x * blockDim.x + threadIdx.x;
    if (i >= RE) return;
    int r = i / EE, s = src[i], d = dst[i];
    int row = r * NN + d;
    int pos  = atomicAdd(&g_cursor[row], 1);
    int slot = g_offs[row] + pos;
    g_csrc[slot] = s;
    g_cw[slot]   = g_norm_src[r * NN + s];
    atomicAdd(&g_c[r * NN + s], g_norm_dst[row]);
}

// warp per (relation, dst) row: Y[n, r*128+f] = nd * sum_e w_e * x[src_e][f],
// emitted as bf16 hi/lo pair for the tensor-core GEMM.
__global__ void k_agg(const float* __restrict__ x) {
    int w = (blockIdx.x * blockDim.x + threadIdx.x) >> 5;
    int lane = threadIdx.x & 31;
    if (w >= RN) return;
    int beg = g_offs[w], end = g_offs[w + 1];
    const float4* x4 = (const float4*)x;
    float4 acc = make_float4(0.f, 0.f, 0.f, 0.f);
    for (int j = beg; j < end; j++) {
        int   s  = g_csrc[j];
        float wt = g_cw[j];
        float4 xv = x4[(size_t)s * 32 + lane];
        acc.x += wt * xv.x; acc.y += wt * xv.y;
        acc.z += wt * xv.z; acc.w += wt * xv.w;
    }
    float nd = g_norm_dst[w];
    int r = w / NN, n = w - r * NN;
    __nv_bfloat16 h[4], l[4];
    bfsplit(acc.x * nd, h[0], l[0]);
    bfsplit(acc.y * nd, h[1], l[1]);
    bfsplit(acc.z * nd, h[2], l[2]);
    bfsplit(acc.w * nd, h[3], l[3]);
    size_t off = (size_t)n * KT + r * FF + lane * 4;
    *(uint2*)&g_Yh[off] = *(uint2*)h;
    *(uint2*)&g_Yl[off] = *(uint2*)l;
}

__global__ void k_bsum1(const float* __restrict__ b1) {
    int t = threadIdx.x;
    float a = 0.f;
#pragma unroll
    for (int r = 0; r < RR; r++) a += b1[r * FF + t];
    g_bsum1[t] = a;
}

__global__ void k_prepB(const float* __restrict__ W1) {
    int i = blockIdx.x * blockDim.x + threadIdx.x;   // 768*128 = 98304
    if (i >= KT * FF) return;
    __nv_bfloat16 h, l;
    bfsplit(W1[i], h, l);
    g_Bh[i] = h; g_Bl[i] = l;
}

// ---------------- tensor-core GEMM: h = relu(Y[100k,768] @ W1[768,128] + b) --
// 3-term bf16 split: AhBh + AhBl + AlBh. Block 128x128, K-tile 32, 8 warps.
__global__ void __launch_bounds__(256, 1) k_gemm() {
    __shared__ __nv_bfloat16 Ash[128][40];   // 80B row stride -> conflict-free
    __shared__ __nv_bfloat16 Asl[128][40];
    __shared__ __nv_bfloat16 Bsh[32][136];   // 272B row stride -> conflict-free
    __shared__ __nv_bfloat16 Bsl[32][136];

    int tid = threadIdx.x, lane = tid & 31, warp = tid >> 5;
    int wm = warp & 3, wn = warp >> 2;       // 4 warps in M, 2 in N
    size_t m0 = (size_t)blockIdx.x * 128;

    float acc[2][8][4];
#pragma unroll
    for (int i = 0; i < 2; i++)
#pragma unroll
        for (int j = 0; j < 8; j++)
#pragma unroll
            for (int q = 0; q < 4; q++) acc[i][j][q] = 0.f;

    // per-lane ldmatrix source addresses (offsets within smem tiles)
    int aRow = wm * 32 + (lane & 15);
    int aColK = (lane >> 4) * 8;            // +8 for k upper half select by lane
    int bKr  = (lane & 7) + ((lane >> 3) & 1) * 8;
    int bCol = wn * 64 + ((lane >> 4) & 1) * 8;

    for (int kt = 0; kt < KT / 32; kt++) {
        int kbase = kt * 32;
#pragma unroll
        for (int u = 0; u < 2; u++) {
            int idx = tid + u * 256;
            int ar = idx >> 2, ac = (idx & 3) * 8;
            size_t ga = (m0 + ar) * (size_t)KT + kbase + ac;
            *(uint4*)&Ash[ar][ac] = *(const uint4*)&g_Yh[ga];
            *(uint4*)&Asl[ar][ac] = *(const uint4*)&g_Yl[ga];
            int br = idx >> 4, bc = (idx & 15) * 8;
            int gb = (kbase + br) * FF + bc;
            *(uint4*)&Bsh[br][bc] = *(const uint4*)&g_Bh[gb];
            *(uint4*)&Bsl[br][bc] = *(const uint4*)&g_Bl[gb];
        }
        __syncthreads();

#pragma unroll
        for (int kc = 0; kc < 2; kc++) {
            uint32_t ah[2][4], al[2][4], bh[8][2], bl[8][2];
#pragma unroll
            for (int i = 0; i < 2; i++) {
                ldmx4(ah[i], smem_u32(&Ash[aRow + i * 16][kc * 16 + aColK]));
                ldmx4(al[i], smem_u32(&Asl[aRow + i * 16][kc * 16 + aColK]));
            }
#pragma unroll
            for (int p = 0; p < 4; p++) {
                uint32_t r4[4];
                ldmx4t(r4, smem_u32(&Bsh[kc * 16 + bKr][bCol + p * 16]));
                bh[2 * p][0] = r4[0]; bh[2 * p][1] = r4[1];
                bh[2 * p + 1][0] = r4[2]; bh[2 * p + 1][1] = r4[3];
                ldmx4t(r4, smem_u32(&Bsl[kc * 16 + bKr][bCol + p * 16]));
                bl[2 * p][0] = r4[0]; bl[2 * p][1] = r4[1];
                bl[2 * p + 1][0] = r4[2]; bl[2 * p + 1][1] = r4[3];
            }
#pragma unroll
            for (int i = 0; i < 2; i++)
#pragma unroll
                for (int j = 0; j < 8; j++) {
                    mma16816(acc[i][j], ah[i], bh[j]);
                    mma16816(acc[i][j], ah[i], bl[j]);
                    mma16816(acc[i][j], al[i], bh[j]);
                }
        }
        __syncthreads();
    }

    // epilogue: bias + relu, guarded stores
    int rBase = (int)m0 + wm * 32 + (lane >> 2);
    int cBase = wn * 64 + (lane & 3) * 2;
#pragma unroll
    for (int i = 0; i < 2; i++) {
        int ra = rBase + i * 16;
        int rb = ra + 8;
#pragma unroll
        for (int j = 0; j < 8; j++) {
            int col = cBase + j * 8;
            float b0 = g_bsum1[col], b1 = g_bsum1[col + 1];
            if (ra < NN) {
                g_h[(size_t)ra * FF + col]     = fmaxf(acc[i][j][0] + b0, 0.f);
                g_h[(size_t)ra * FF + col + 1] = fmaxf(acc[i][j][1] + b1, 0.f);
            }
            if (rb < NN) {
                g_h[(size_t)rb * FF + col]     = fmaxf(acc[i][j][2] + b0, 0.f);
                g_h[(size_t)rb * FF + col + 1] = fmaxf(acc[i][j][3] + b1, 0.f);
            }
        }
    }
}

// s[r][f] = sum_n (norm_src_r[n]*c_r[n]) * h[n][f]
__global__ void k_reduce() {
    __shared__ float wc[RR][128];
    int t = threadIdx.x;
    int base = blockIdx.x * 128;
    int n = base + t;
#pragma unroll
    for (int r = 0; r < RR; r++)
        wc[r][t] = (n < NN) ? g_norm_src[r * NN + n] * g_c[r * NN + n] : 0.f;
    __syncthreads();
    float acc[RR] = {0.f, 0.f, 0.f, 0.f, 0.f, 0.f};
    int lim = min(128, NN - base);
    for (int ni = 0; ni < lim; ni++) {
        float hv = g_h[(size_t)(base + ni) * FF + t];
#pragma unroll
        for (int r = 0; r < RR; r++) acc[r] += wc[r][ni] * hv;
    }
#pragma unroll
    for (int r = 0; r < RR; r++) atomicAdd(&g_s[r * FF + t], acc[r]);
}

__global__ void k_final(const float* __restrict__ W2, const float* __restrict__ b2,
                        const float* __restrict__ Wc, const float* __restrict__ bc,
                        float* __restrict__ out) {
    __shared__ float g[FF];
    int f = threadIdx.x;
    float acc = 0.f;
    for (int rk = 0; rk < RR * FF; rk++)
        acc += g_s[rk] * W2[(size_t)rk * FF + f];
    float gb = 0.f;
#pragma unroll
    for (int r = 0; r < RR; r++) gb += b2[r * FF + f];
    g[f] = acc * (1.f / NN) + gb;
    __syncthreads();
    if (f < 2) {
        float o = bc[f];
        for (int k = 0; k < FF; k++) o += g[k] * Wc[k * 2 + f];
        out[f] = o;
    }
}

// ---------------- launch ----------------
extern "C" void kernel_launch(void* const* d_in, const int* in_sizes, int n_in,
                              void* d_out, int out_size) {
    const float* x    = (const float*)d_in[0];
    const int*   esrc = (const int*)  d_in[1];
    const int*   edst = (const int*)  d_in[2];
    const float* W1   = (const float*)d_in[3];
    const float* b1   = (const float*)d_in[4];
    const float* W2   = (const float*)d_in[5];
    const float* b2   = (const float*)d_in[6];
    const float* Wc   = (const float*)d_in[7];
    const float* bc   = (const float*)d_in[8];
    float* out = (float*)d_out;

    void *p_do, *p_di, *p_cur, *p_c, *p_s;
    cudaGetSymbolAddress(&p_do,  g_deg_out);
    cudaGetSymbolAddress(&p_di,  g_deg_in);
    cudaGetSymbolAddress(&p_cur, g_cursor);
    cudaGetSymbolAddress(&p_c,   g_c);
    cudaGetSymbolAddress(&p_s,   g_s);
    cudaMemsetAsync(p_do,  0, (size_t)RN * 4, 0);
    cudaMemsetAsync(p_di,  0, (size_t)RN * 4, 0);
    cudaMemsetAsync(p_cur, 0, (size_t)RN * 4, 0);
    cudaMemsetAsync(p_c,   0, (size_t)RN * 4, 0);
    cudaMemsetAsync(p_s,   0, (size_t)RR * FF * 4, 0);

    k_deg  <<<(RE + 255) / 256, 256>>>(esrc, edst);
    k_norm <<<(RN + 255) / 256, 256>>>();
    k_scan1<<<NB, 1024>>>();
    k_scan2<<<1, 1024>>>();
    k_scan3<<<NB, 1024>>>();
    k_prepB<<<(KT * FF + 255) / 256, 256>>>(W1);
    k_bsum1<<<1, FF>>>(b1);
    k_fill <<<(RE + 255) / 256, 256>>>(esrc, edst);
    k_agg  <<<RN / 8, 256>>>(x);
    k_gemm <<<(NN + 127) / 128, 256>>>();
    k_reduce<<<(NN + 127) / 128, 128>>>();
    k_final<<<1, FF>>>(W2, b2, Wc, bc, out);
}

// round 10
// speedup vs baseline: 2.0070x; 1.4123x over previous
#include <cuda_runtime.h>
#include <cuda_bf16.h>
#include <cstdint>
#include <cstddef>

#define NN 100000
#define RR 6
#define EE 400000
#define FF 128
#define KT 768          // RR*FF (N dim of Z)
#define RN 600000       // RR*NN
#define RE 2400000      // RR*EE
#define MPAD 100096     // 782*128 padded rows for Xh/Z
#define NB2 98          // ceil(NN/1024)

// ---------------- scratch (device globals; zero-initialized at load) --------
__device__ int   g_deg_out[RN];
__device__ int   g_deg_in[RN];
__device__ float g_norm_src[RN];
__device__ float g_norm_dst[RN];
__device__ int   g_deg2[NN];
__device__ int   g_offs2[NN + 1];
__device__ int   g_bsums[NB2];
__device__ int   g_boffs[NB2];
__device__ int   g_cursor2[NN];
__device__ int   g_epack[RE];      // src | (r<<17)
__device__ float g_ew[RE];         // norm_src_r[src]*norm_dst_r[dst]
__device__ float g_c[RN];          // layer-2 coefficients
__device__ float g_bsum1[FF];
__device__ __nv_bfloat16 g_Xh[(size_t)MPAD * FF];   // x in bf16 (pad rows stay 0)
__device__ __nv_bfloat16 g_Bh[FF * KT];             // W1 repacked [k][r*128+j] hi
__device__ __nv_bfloat16 g_Bl[FF * KT];             // lo residual
__device__ __nv_bfloat16 g_Z[(size_t)MPAD * KT];    // Z = X @ W1cat, bf16
__device__ float g_h[(size_t)NN * FF];              // layer-1 output (post-relu)
__device__ float g_s[RR * FF];                      // layer-2 pooled vectors

// ---------------- helpers ----------------------------------------------------
__device__ __forceinline__ uint32_t smem_u32(const void* p) {
    return (uint32_t)__cvta_generic_to_shared(p);
}
__device__ __forceinline__ void ldmx4(uint32_t* r, uint32_t addr) {
    asm volatile("ldmatrix.sync.aligned.m8n8.x4.shared.b16 {%0,%1,%2,%3}, [%4];"
        : "=r"(r[0]), "=r"(r[1]), "=r"(r[2]), "=r"(r[3]) : "r"(addr));
}
__device__ __forceinline__ void ldmx4t(uint32_t* r, uint32_t addr) {
    asm volatile("ldmatrix.sync.aligned.m8n8.x4.trans.shared.b16 {%0,%1,%2,%3}, [%4];"
        : "=r"(r[0]), "=r"(r[1]), "=r"(r[2]), "=r"(r[3]) : "r"(addr));
}
__device__ __forceinline__ void mma16816(float* d, const uint32_t* a, const uint32_t* b) {
    asm volatile(
        "mma.sync.aligned.m16n8k16.row.col.f32.bf16.bf16.f32 "
        "{%0,%1,%2,%3}, {%4,%5,%6,%7}, {%8,%9}, {%0,%1,%2,%3};"
        : "+f"(d[0]), "+f"(d[1]), "+f"(d[2]), "+f"(d[3])
        : "r"(a[0]), "r"(a[1]), "r"(a[2]), "r"(a[3]), "r"(b[0]), "r"(b[1]));
}
__device__ __forceinline__ void bfsplit(float v, __nv_bfloat16& h, __nv_bfloat16& l) {
    h = __float2bfloat16_rn(v);
    l = __float2bfloat16_rn(v - __bfloat162float(h));
}
__device__ __forceinline__ uint32_t packbf2(float a, float b) {
    __nv_bfloat16 ha = __float2bfloat16_rn(a), hb = __float2bfloat16_rn(b);
    return (uint32_t)__bfloat16_as_ushort(ha) | ((uint32_t)__bfloat16_as_ushort(hb) << 16);
}

// ---------------- graph prep -------------------------------------------------
__global__ void k_deg(const int* __restrict__ src, const int* __restrict__ dst) {
    int i = blockIdx.x * blockDim.x + threadIdx.x;
    if (i >= RE) return;
    int r = i / EE;
    atomicAdd(&g_deg_out[r * NN + src[i]], 1);
    atomicAdd(&g_deg_in [r * NN + dst[i]], 1);
}

__global__ void k_norm() {
    int i = blockIdx.x * blockDim.x + threadIdx.x;
    if (i >= RN) return;
    int d0 = g_deg_out[i], d1 = g_deg_in[i];
    g_norm_src[i] = d0 > 0 ? rsqrtf((float)d0) : 0.f;
    g_norm_dst[i] = d1 > 0 ? rsqrtf((float)d1) : 0.f;
}

__global__ void k_deg2() {
    int n = blockIdx.x * blockDim.x + threadIdx.x;
    if (n >= NN) return;
    int a = 0;
#pragma unroll
    for (int r = 0; r < RR; r++) a += g_deg_in[r * NN + n];
    g_deg2[n] = a;
}

__global__ void k_dscan1() {
    __shared__ int s[1024];
    int t = threadIdx.x, i = blockIdx.x * 1024 + t;
    int v = (i < NN) ? g_deg2[i] : 0;
    s[t] = v; __syncthreads();
    for (int d = 1; d < 1024; d <<= 1) {
        int u = (t >= d) ? s[t - d] : 0;
        __syncthreads();
        s[t] += u; __syncthreads();
    }
    if (i < NN) g_offs2[i] = s[t] - v;
    if (t == 1023) g_bsums[blockIdx.x] = s[1023];
}

__global__ void k_dscan2() {
    __shared__ int s[128];
    int t = threadIdx.x;
    int v = (t < NB2) ? g_bsums[t] : 0;
    s[t] = v; __syncthreads();
    for (int d = 1; d < 128; d <<= 1) {
        int u = (t >= d) ? s[t - d] : 0;
        __syncthreads();
        s[t] += u; __syncthreads();
    }
    if (t < NB2) g_boffs[t] = s[t] - v;
}

__global__ void k_dscan3() {
    int t = threadIdx.x, i = blockIdx.x * 1024 + t;
    if (i < NN) g_offs2[i] += g_boffs[blockIdx.x];
    if (i == 0) g_offs2[NN] = RE;
}

// merged CSR keyed by dst; also accumulates layer-2 coefficients
__global__ void k_fill2(const int* __restrict__ src, const int* __restrict__ dst) {
    int i = blockIdx.x * blockDim.x + threadIdx.x;
    if (i >= RE) return;
    int r = i / EE, s = src[i], d = dst[i];
    float nd = g_norm_dst[r * NN + d];
    int pos  = atomicAdd(&g_cursor2[d], 1);
    int slot = g_offs2[d] + pos;
    g_epack[slot] = s | (r << 17);
    g_ew[slot]    = g_norm_src[r * NN + s] * nd;
    atomicAdd(&g_c[r * NN + s], nd);
}

// ---------------- operand prep ----------------------------------------------
__global__ void k_prepX(const float* __restrict__ x) {
    int i = blockIdx.x * blockDim.x + threadIdx.x;   // NN*FF/4 = 3.2M
    if (i >= NN * FF / 4) return;
    float4 v = ((const float4*)x)[i];
    uint2 o;
    o.x = packbf2(v.x, v.y);
    o.y = packbf2(v.z, v.w);
    ((uint2*)g_Xh)[i] = o;
}

__global__ void k_prepB(const float* __restrict__ W1) {
    int i = blockIdx.x * blockDim.x + threadIdx.x;   // 6*128*128 = 98304
    if (i >= RR * FF * FF) return;
    int r = i / (FF * FF), rem = i % (FF * FF);
    int k = rem / FF, j = rem % FF;
    __nv_bfloat16 h, l;
    bfsplit(W1[i], h, l);
    int o = k * KT + r * FF + j;
    g_Bh[o] = h; g_Bl[o] = l;
}

__global__ void k_bsum1(const float* __restrict__ b1) {
    int t = threadIdx.x;
    float a = 0.f;
#pragma unroll
    for (int r = 0; r < RR; r++) a += b1[r * FF + t];
    g_bsum1[t] = a;
}

// ---------------- GEMM: Z[100k,768] = Xh[100k,128] @ B[128,768], 2-term -----
// Block 128x128 (grid 782 x 6), K=128 in 4 tiles of 32, 8 warps (4M x 2N).
__global__ void __launch_bounds__(256, 2) k_gemmZ() {
    __shared__ __nv_bfloat16 Ash[128][40];
    __shared__ __nv_bfloat16 Bsh[32][136];
    __shared__ __nv_bfloat16 Bsl[32][136];

    int tid = threadIdx.x, lane = tid & 31, warp = tid >> 5;
    int wm = warp & 3, wn = warp >> 2;
    size_t m0 = (size_t)blockIdx.x * 128;
    int n0 = blockIdx.y * 128;

    float acc[2][8][4];
#pragma unroll
    for (int i = 0; i < 2; i++)
#pragma unroll
        for (int j = 0; j < 8; j++)
#pragma unroll
            for (int q = 0; q < 4; q++) acc[i][j][q] = 0.f;

    int aRow = wm * 32 + (lane & 15);
    int aColK = (lane >> 4) * 8;
    int bKr  = (lane & 7) + ((lane >> 3) & 1) * 8;
    int bCol = wn * 64 + ((lane >> 4) & 1) * 8;

#pragma unroll
    for (int kt = 0; kt < 4; kt++) {
        int kbase = kt * 32;
#pragma unroll
        for (int u = 0; u < 2; u++) {
            int idx = tid + u * 256;
            int ar = idx >> 2, ac = (idx & 3) * 8;
            *(uint4*)&Ash[ar][ac] = *(const uint4*)&g_Xh[(m0 + ar) * FF + kbase + ac];
            int br = idx >> 4, bc = (idx & 15) * 8;
            int gb = (kbase + br) * KT + n0 + bc;
            *(uint4*)&Bsh[br][bc] = *(const uint4*)&g_Bh[gb];
            *(uint4*)&Bsl[br][bc] = *(const uint4*)&g_Bl[gb];
        }
        __syncthreads();

#pragma unroll
        for (int kc = 0; kc < 2; kc++) {
            uint32_t ah[2][4], bh[8][2], bl[8][2];
#pragma unroll
            for (int i = 0; i < 2; i++)
                ldmx4(ah[i], smem_u32(&Ash[aRow + i * 16][kc * 16 + aColK]));
#pragma unroll
            for (int p = 0; p < 4; p++) {
                uint32_t r4[4];
                ldmx4t(r4, smem_u32(&Bsh[kc * 16 + bKr][bCol + p * 16]));
                bh[2 * p][0] = r4[0]; bh[2 * p][1] = r4[1];
                bh[2 * p + 1][0] = r4[2]; bh[2 * p + 1][1] = r4[3];
                ldmx4t(r4, smem_u32(&Bsl[kc * 16 + bKr][bCol + p * 16]));
                bl[2 * p][0] = r4[0]; bl[2 * p][1] = r4[1];
                bl[2 * p + 1][0] = r4[2]; bl[2 * p + 1][1] = r4[3];
            }
#pragma unroll
            for (int i = 0; i < 2; i++)
#pragma unroll
                for (int j = 0; j < 8; j++) {
                    mma16816(acc[i][j], ah[i], bh[j]);
                    mma16816(acc[i][j], ah[i], bl[j]);
                }
        }
        __syncthreads();
    }

    // epilogue: store Z as bf16 (rows padded, no guard)
    size_t rBase = m0 + wm * 32 + (lane >> 2);
    int cBase = n0 + wn * 64 + (lane & 3) * 2;
#pragma unroll
    for (int i = 0; i < 2; i++) {
        size_t ra = rBase + i * 16, rb = ra + 8;
#pragma unroll
        for (int j = 0; j < 8; j++) {
            int col = cBase + j * 8;
            *(uint32_t*)&g_Z[ra * KT + col] = packbf2(acc[i][j][0], acc[i][j][1]);
            *(uint32_t*)&g_Z[rb * KT + col] = packbf2(acc[i][j][2], acc[i][j][3]);
        }
    }
}

// ---------------- aggregation: h = relu(sum_e w_e * Z[src_e, r_e] + bsum1) ---
__global__ void k_agg2() {
    int w = (blockIdx.x * blockDim.x + threadIdx.x) >> 5;   // dst node
    int lane = threadIdx.x & 31;
    if (w >= NN) return;
    int beg = g_offs2[w], end = g_offs2[w + 1];
    float a0 = 0.f, a1 = 0.f, a2 = 0.f, a3 = 0.f;
    int j = beg;
    for (; j + 1 < end; j += 2) {
        int   p0 = g_epack[j],     p1 = g_epack[j + 1];
        float w0 = g_ew[j],        w1 = g_ew[j + 1];
        size_t o0 = (size_t)(p0 & 131071) * KT + (p0 >> 17) * FF + lane * 4;
        size_t o1 = (size_t)(p1 & 131071) * KT + (p1 >> 17) * FF + lane * 4;
        uint2 z0 = *(const uint2*)&g_Z[o0];
        uint2 z1 = *(const uint2*)&g_Z[o1];
        float2 u0 = __bfloat1622float2(*(__nv_bfloat162*)&z0.x);
        float2 u1 = __bfloat1622float2(*(__nv_bfloat162*)&z0.y);
        a0 += w0 * u0.x; a1 += w0 * u0.y; a2 += w0 * u1.x; a3 += w0 * u1.y;
        float2 v0 = __bfloat1622float2(*(__nv_bfloat162*)&z1.x);
        float2 v1 = __bfloat1622float2(*(__nv_bfloat162*)&z1.y);
        a0 += w1 * v0.x; a1 += w1 * v0.y; a2 += w1 * v1.x; a3 += w1 * v1.y;
    }
    if (j < end) {
        int   p = g_epack[j];
        float wt = g_ew[j];
        size_t o = (size_t)(p & 131071) * KT + (p >> 17) * FF + lane * 4;
        uint2 z = *(const uint2*)&g_Z[o];
        float2 u0 = __bfloat1622float2(*(__nv_bfloat162*)&z.x);
        float2 u1 = __bfloat1622float2(*(__nv_bfloat162*)&z.y);
        a0 += wt * u0.x; a1 += wt * u0.y; a2 += wt * u1.x; a3 += wt * u1.y;
    }
    float4 bb = *(const float4*)&g_bsum1[lane * 4];
    float4 o;
    o.x = fmaxf(a0 + bb.x, 0.f);
    o.y = fmaxf(a1 + bb.y, 0.f);
    o.z = fmaxf(a2 + bb.z, 0.f);
    o.w = fmaxf(a3 + bb.w, 0.f);
    *(float4*)&g_h[(size_t)w * FF + lane * 4] = o;
}

// ---------------- layer-2 collapse + classifier ------------------------------
__global__ void k_reduce() {
    __shared__ float wc[RR][128];
    int t = threadIdx.x;
    int base = blockIdx.x * 128;
    int n = base + t;
#pragma unroll
    for (int r = 0; r < RR; r++)
        wc[r][t] = (n < NN) ? g_norm_src[r * NN + n] * g_c[r * NN + n] : 0.f;
    __syncthreads();
    float acc[RR] = {0.f, 0.f, 0.f, 0.f, 0.f, 0.f};
    int lim = min(128, NN - base);
    for (int ni = 0; ni < lim; ni++) {
        float hv = g_h[(size_t)(base + ni) * FF + t];
#pragma unroll
        for (int r = 0; r < RR; r++) acc[r] += wc[r][ni] * hv;
    }
#pragma unroll
    for (int r = 0; r < RR; r++) atomicAdd(&g_s[r * FF + t], acc[r]);
}

__global__ void k_final(const float* __restrict__ W2, const float* __restrict__ b2,
                        const float* __restrict__ Wc, const float* __restrict__ bc,
                        float* __restrict__ out) {
    __shared__ float g[FF];
    int f = threadIdx.x;
    float acc = 0.f;
    for (int rk = 0; rk < RR * FF; rk++)
        acc += g_s[rk] * W2[(size_t)rk * FF + f];
    float gb = 0.f;
#pragma unroll
    for (int r = 0; r < RR; r++) gb += b2[r * FF + f];
    g[f] = acc * (1.f / NN) + gb;
    __syncthreads();
    if (f < 2) {
        float o = bc[f];
        for (int k = 0; k < FF; k++) o += g[k] * Wc[k * 2 + f];
        out[f] = o;
    }
}

// ---------------- launch ----------------
extern "C" void kernel_launch(void* const* d_in, const int* in_sizes, int n_in,
                              void* d_out, int out_size) {
    const float* x    = (const float*)d_in[0];
    const int*   esrc = (const int*)  d_in[1];
    const int*   edst = (const int*)  d_in[2];
    const float* W1   = (const float*)d_in[3];
    const float* b1   = (const float*)d_in[4];
    const float* W2   = (const float*)d_in[5];
    const float* b2   = (const float*)d_in[6];
    const float* Wc   = (const float*)d_in[7];
    const float* bc   = (const float*)d_in[8];
    float* out = (float*)d_out;

    void *p_do, *p_di, *p_cur, *p_c, *p_s;
    cudaGetSymbolAddress(&p_do,  g_deg_out);
    cudaGetSymbolAddress(&p_di,  g_deg_in);
    cudaGetSymbolAddress(&p_cur, g_cursor2);
    cudaGetSymbolAddress(&p_c,   g_c);
    cudaGetSymbolAddress(&p_s,   g_s);
    cudaMemsetAsync(p_do,  0, (size_t)RN * 4, 0);
    cudaMemsetAsync(p_di,  0, (size_t)RN * 4, 0);
    cudaMemsetAsync(p_cur, 0, (size_t)NN * 4, 0);
    cudaMemsetAsync(p_c,   0, (size_t)RN * 4, 0);
    cudaMemsetAsync(p_s,   0, (size_t)RR * FF * 4, 0);

    k_prepX<<<(NN * FF / 4 + 255) / 256, 256>>>(x);
    k_prepB<<<(RR * FF * FF + 255) / 256, 256>>>(W1);
    k_bsum1<<<1, FF>>>(b1);
    k_deg  <<<(RE + 255) / 256, 256>>>(esrc, edst);
    k_norm <<<(RN + 255) / 256, 256>>>();
    k_deg2 <<<(NN + 255) / 256, 256>>>();
    k_dscan1<<<NB2, 1024>>>();
    k_dscan2<<<1, 128>>>();
    k_dscan3<<<NB2, 1024>>>();
    k_fill2<<<(RE + 255) / 256, 256>>>(esrc, edst);
    k_gemmZ<<<dim3(782, 6), 256>>>();
    k_agg2 <<<(NN * 32 + 255) / 256, 256>>>();
    k_reduce<<<(NN + 127) / 128, 128>>>();
    k_final<<<1, FF>>>(W2, b2, Wc, bc, out);
}

// round 12
// speedup vs baseline: 2.0938x; 1.0432x over previous
#include <cuda_runtime.h>
#include <cuda_bf16.h>
#include <cstdint>
#include <cstddef>

#define NN 100000
#define RR 6
#define EE 400000
#define FF 128
#define KT 768          // RR*FF (N dim of Z)
#define RN 600000       // RR*NN
#define RE 2400000      // RR*EE
#define MPAD 100096     // 782*128 padded rows for Xh/Z
#define NB2 98          // ceil(NN/1024)

// ---------------- scratch (device globals; zero-initialized at load) --------
__device__ int   g_deg_out[RN];
__device__ int   g_deg_in[RN];
__device__ float g_norm_src[RN];
__device__ float g_norm_dst[RN];
__device__ int   g_deg2[NN];
__device__ int   g_offs2[NN + 1];
__device__ int   g_bsums[NB2];
__device__ int   g_boffs[NB2];
__device__ int   g_cursor2[NN];
__device__ int   g_epack[RE];      // src | (r<<17)
__device__ float g_ew[RE];         // norm_src_r[src]*norm_dst_r[dst]
__device__ float g_c[RN];          // layer-2 coefficients
__device__ float g_bsum1[FF];
__device__ __nv_bfloat16 g_Xh[(size_t)MPAD * FF];   // x in bf16 (pad rows stay 0)
__device__ __nv_bfloat16 g_Bh[FF * KT];             // W1 repacked [k][r*128+j] hi
__device__ __nv_bfloat16 g_Bl[FF * KT];             // lo residual
__device__ __nv_bfloat16 g_Z[(size_t)MPAD * KT];    // Z = X @ W1cat, bf16
__device__ float g_h[(size_t)NN * FF];              // layer-1 output (post-relu)
__device__ float g_s[RR * FF];                      // layer-2 pooled vectors

// ---- side stream + events, created at load time (before harness baseline) --
static cudaStream_t g_s2;
static cudaEvent_t  g_evF, g_evJ;
namespace {
struct StreamInit {
    StreamInit() {
        cudaStreamCreateWithFlags(&g_s2, cudaStreamNonBlocking);
        cudaEventCreateWithFlags(&g_evF, cudaEventDisableTiming);
        cudaEventCreateWithFlags(&g_evJ, cudaEventDisableTiming);
    }
};
StreamInit s_streamInit;
}

// ---------------- helpers ----------------------------------------------------
__device__ __forceinline__ uint32_t smem_u32(const void* p) {
    return (uint32_t)__cvta_generic_to_shared(p);
}
__device__ __forceinline__ void ldmx4(uint32_t* r, uint32_t addr) {
    asm volatile("ldmatrix.sync.aligned.m8n8.x4.shared.b16 {%0,%1,%2,%3}, [%4];"
        : "=r"(r[0]), "=r"(r[1]), "=r"(r[2]), "=r"(r[3]) : "r"(addr));
}
__device__ __forceinline__ void ldmx4t(uint32_t* r, uint32_t addr) {
    asm volatile("ldmatrix.sync.aligned.m8n8.x4.trans.shared.b16 {%0,%1,%2,%3}, [%4];"
        : "=r"(r[0]), "=r"(r[1]), "=r"(r[2]), "=r"(r[3]) : "r"(addr));
}
__device__ __forceinline__ void mma16816(float* d, const uint32_t* a, const uint32_t* b) {
    asm volatile(
        "mma.sync.aligned.m16n8k16.row.col.f32.bf16.bf16.f32 "
        "{%0,%1,%2,%3}, {%4,%5,%6,%7}, {%8,%9}, {%0,%1,%2,%3};"
        : "+f"(d[0]), "+f"(d[1]), "+f"(d[2]), "+f"(d[3])
        : "r"(a[0]), "r"(a[1]), "r"(a[2]), "r"(a[3]), "r"(b[0]), "r"(b[1]));
}
__device__ __forceinline__ void bfsplit(float v, __nv_bfloat16& h, __nv_bfloat16& l) {
    h = __float2bfloat16_rn(v);
    l = __float2bfloat16_rn(v - __bfloat162float(h));
}
__device__ __forceinline__ uint32_t packbf2(float a, float b) {
    __nv_bfloat16 ha = __float2bfloat16_rn(a), hb = __float2bfloat16_rn(b);
    return (uint32_t)__bfloat16_as_ushort(ha) | ((uint32_t)__bfloat16_as_ushort(hb) << 16);
}

// ---------------- graph prep -------------------------------------------------
__global__ void k_deg(const int* __restrict__ src, const int* __restrict__ dst) {
    int i = blockIdx.x * blockDim.x + threadIdx.x;
    if (i >= RE) return;
    int r = i / EE;
    atomicAdd(&g_deg_out[r * NN + src[i]], 1);
    atomicAdd(&g_deg_in [r * NN + dst[i]], 1);
}

__global__ void k_norm() {
    int i = blockIdx.x * blockDim.x + threadIdx.x;
    if (i >= RN) return;
    int d0 = g_deg_out[i], d1 = g_deg_in[i];
    g_norm_src[i] = d0 > 0 ? rsqrtf((float)d0) : 0.f;
    g_norm_dst[i] = d1 > 0 ? rsqrtf((float)d1) : 0.f;
}

__global__ void k_deg2() {
    int n = blockIdx.x * blockDim.x + threadIdx.x;
    if (n >= NN) return;
    int a = 0;
#pragma unroll
    for (int r = 0; r < RR; r++) a += g_deg_in[r * NN + n];
    g_deg2[n] = a;
}

__global__ void k_dscan1() {
    __shared__ int s[1024];
    int t = threadIdx.x, i = blockIdx.x * 1024 + t;
    int v = (i < NN) ? g_deg2[i] : 0;
    s[t] = v; __syncthreads();
    for (int d = 1; d < 1024; d <<= 1) {
        int u = (t >= d) ? s[t - d] : 0;
        __syncthreads();
        s[t] += u; __syncthreads();
    }
    if (i < NN) g_offs2[i] = s[t] - v;
    if (t == 1023) g_bsums[blockIdx.x] = s[1023];
}

__global__ void k_dscan2() {
    __shared__ int s[128];
    int t = threadIdx.x;
    int v = (t < NB2) ? g_bsums[t] : 0;
    s[t] = v; __syncthreads();
    for (int d = 1; d < 128; d <<= 1) {
        int u = (t >= d) ? s[t - d] : 0;
        __syncthreads();
        s[t] += u; __syncthreads();
    }
    if (t < NB2) g_boffs[t] = s[t] - v;
}

__global__ void k_dscan3() {
    int t = threadIdx.x, i = blockIdx.x * 1024 + t;
    if (i < NN) g_offs2[i] += g_boffs[blockIdx.x];
    if (i == 0) g_offs2[NN] = RE;
}

// merged CSR keyed by dst; also accumulates layer-2 coefficients
__global__ void k_fill2(const int* __restrict__ src, const int* __restrict__ dst) {
    int i = blockIdx.x * blockDim.x + threadIdx.x;
    if (i >= RE) return;
    int r = i / EE, s = src[i], d = dst[i];
    float nd = g_norm_dst[r * NN + d];
    int pos  = atomicAdd(&g_cursor2[d], 1);
    int slot = g_offs2[d] + pos;
    g_epack[slot] = s | (r << 17);
    g_ew[slot]    = g_norm_src[r * NN + s] * nd;
    atomicAdd(&g_c[r * NN + s], nd);
}

// ---------------- operand prep ----------------------------------------------
__global__ void k_prepX(const float* __restrict__ x) {
    int i = blockIdx.x * blockDim.x + threadIdx.x;   // NN*FF/4 = 3.2M
    if (i >= NN * FF / 4) return;
    float4 v = ((const float4*)x)[i];
    uint2 o;
    o.x = packbf2(v.x, v.y);
    o.y = packbf2(v.z, v.w);
    ((uint2*)g_Xh)[i] = o;
}

__global__ void k_prepB(const float* __restrict__ W1) {
    int i = blockIdx.x * blockDim.x + threadIdx.x;   // 6*128*128 = 98304
    if (i >= RR * FF * FF) return;
    int r = i / (FF * FF), rem = i % (FF * FF);
    int k = rem / FF, j = rem % FF;
    __nv_bfloat16 h, l;
    bfsplit(W1[i], h, l);
    int o = k * KT + r * FF + j;
    g_Bh[o] = h; g_Bl[o] = l;
}

__global__ void k_bsum1(const float* __restrict__ b1) {
    int t = threadIdx.x;
    float a = 0.f;
#pragma unroll
    for (int r = 0; r < RR; r++) a += b1[r * FF + t];
    g_bsum1[t] = a;
}

// ---------------- GEMM: Z[100k,768] = Xh[100k,128] @ B[128,768], 2-term -----
// Block 128x128 (grid 782 x 6), K=128 in 4 tiles of 32, 8 warps (4M x 2N).
__global__ void __launch_bounds__(256, 2) k_gemmZ() {
    __shared__ __nv_bfloat16 Ash[128][40];
    __shared__ __nv_bfloat16 Bsh[32][136];
    __shared__ __nv_bfloat16 Bsl[32][136];

    int tid = threadIdx.x, lane = tid & 31, warp = tid >> 5;
    int wm = warp & 3, wn = warp >> 2;
    size_t m0 = (size_t)blockIdx.x * 128;
    int n0 = blockIdx.y * 128;

    float acc[2][8][4];
#pragma unroll
    for (int i = 0; i < 2; i++)
#pragma unroll
        for (int j = 0; j < 8; j++)
#pragma unroll
            for (int q = 0; q < 4; q++) acc[i][j][q] = 0.f;

    int aRow = wm * 32 + (lane & 15);
    int aColK = (lane >> 4) * 8;
    int bKr  = (lane & 7) + ((lane >> 3) & 1) * 8;
    int bCol = wn * 64 + ((lane >> 4) & 1) * 8;

#pragma unroll
    for (int kt = 0; kt < 4; kt++) {
        int kbase = kt * 32;
#pragma unroll
        for (int u = 0; u < 2; u++) {
            int idx = tid + u * 256;
            int ar = idx >> 2, ac = (idx & 3) * 8;
            *(uint4*)&Ash[ar][ac] = *(const uint4*)&g_Xh[(m0 + ar) * FF + kbase + ac];
            int br = idx >> 4, bc = (idx & 15) * 8;
            int gb = (kbase + br) * KT + n0 + bc;
            *(uint4*)&Bsh[br][bc] = *(const uint4*)&g_Bh[gb];
            *(uint4*)&Bsl[br][bc] = *(const uint4*)&g_Bl[gb];
        }
        __syncthreads();

#pragma unroll
        for (int kc = 0; kc < 2; kc++) {
            uint32_t ah[2][4], bh[8][2], bl[8][2];
#pragma unroll
            for (int i = 0; i < 2; i++)
                ldmx4(ah[i], smem_u32(&Ash[aRow + i * 16][kc * 16 + aColK]));
#pragma unroll
            for (int p = 0; p < 4; p++) {
                uint32_t r4[4];
                ldmx4t(r4, smem_u32(&Bsh[kc * 16 + bKr][bCol + p * 16]));
                bh[2 * p][0] = r4[0]; bh[2 * p][1] = r4[1];
                bh[2 * p + 1][0] = r4[2]; bh[2 * p + 1][1] = r4[3];
                ldmx4t(r4, smem_u32(&Bsl[kc * 16 + bKr][bCol + p * 16]));
                bl[2 * p][0] = r4[0]; bl[2 * p][1] = r4[1];
                bl[2 * p + 1][0] = r4[2]; bl[2 * p + 1][1] = r4[3];
            }
#pragma unroll
            for (int i = 0; i < 2; i++)
#pragma unroll
                for (int j = 0; j < 8; j++) {
                    mma16816(acc[i][j], ah[i], bh[j]);
                    mma16816(acc[i][j], ah[i], bl[j]);
                }
        }
        __syncthreads();
    }

    // epilogue: store Z as bf16 (rows padded, no guard)
    size_t rBase = m0 + wm * 32 + (lane >> 2);
    int cBase = n0 + wn * 64 + (lane & 3) * 2;
#pragma unroll
    for (int i = 0; i < 2; i++) {
        size_t ra = rBase + i * 16, rb = ra + 8;
#pragma unroll
        for (int j = 0; j < 8; j++) {
            int col = cBase + j * 8;
            *(uint32_t*)&g_Z[ra * KT + col] = packbf2(acc[i][j][0], acc[i][j][1]);
            *(uint32_t*)&g_Z[rb * KT + col] = packbf2(acc[i][j][2], acc[i][j][3]);
        }
    }
}

// ---------------- aggregation: h = relu(sum_e w_e * Z[src_e, r_e] + bsum1) ---
__global__ void k_agg2() {
    int w = (blockIdx.x * blockDim.x + threadIdx.x) >> 5;   // dst node
    int lane = threadIdx.x & 31;
    if (w >= NN) return;
    int beg = g_offs2[w], end = g_offs2[w + 1];
    float a0 = 0.f, a1 = 0.f, a2 = 0.f, a3 = 0.f;
    int j = beg;
    for (; j + 1 < end; j += 2) {
        int   p0 = g_epack[j],     p1 = g_epack[j + 1];
        float w0 = g_ew[j],        w1 = g_ew[j + 1];
        size_t o0 = (size_t)(p0 & 131071) * KT + (p0 >> 17) * FF + lane * 4;
        size_t o1 = (size_t)(p1 & 131071) * KT + (p1 >> 17) * FF + lane * 4;
        uint2 z0 = *(const uint2*)&g_Z[o0];
        uint2 z1 = *(const uint2*)&g_Z[o1];
        float2 u0 = __bfloat1622float2(*(__nv_bfloat162*)&z0.x);
        float2 u1 = __bfloat1622float2(*(__nv_bfloat162*)&z0.y);
        a0 += w0 * u0.x; a1 += w0 * u0.y; a2 += w0 * u1.x; a3 += w0 * u1.y;
        float2 v0 = __bfloat1622float2(*(__nv_bfloat162*)&z1.x);
        float2 v1 = __bfloat1622float2(*(__nv_bfloat162*)&z1.y);
        a0 += w1 * v0.x; a1 += w1 * v0.y; a2 += w1 * v1.x; a3 += w1 * v1.y;
    }
    if (j < end) {
        int   p = g_epack[j];
        float wt = g_ew[j];
        size_t o = (size_t)(p & 131071) * KT + (p >> 17) * FF + lane * 4;
        uint2 z = *(const uint2*)&g_Z[o];
        float2 u0 = __bfloat1622float2(*(__nv_bfloat162*)&z.x);
        float2 u1 = __bfloat1622float2(*(__nv_bfloat162*)&z.y);
        a0 += wt * u0.x; a1 += wt * u0.y; a2 += wt * u1.x; a3 += wt * u1.y;
    }
    float4 bb = *(const float4*)&g_bsum1[lane * 4];
    float4 o;
    o.x = fmaxf(a0 + bb.x, 0.f);
    o.y = fmaxf(a1 + bb.y, 0.f);
    o.z = fmaxf(a2 + bb.z, 0.f);
    o.w = fmaxf(a3 + bb.w, 0.f);
    *(float4*)&g_h[(size_t)w * FF + lane * 4] = o;
}

// ---------------- layer-2 collapse + classifier ------------------------------
__global__ void k_reduce() {
    __shared__ float wc[RR][128];
    int t = threadIdx.x;
    int base = blockIdx.x * 128;
    int n = base + t;
#pragma unroll
    for (int r = 0; r < RR; r++)
        wc[r][t] = (n < NN) ? g_norm_src[r * NN + n] * g_c[r * NN + n] : 0.f;
    __syncthreads();
    float acc[RR] = {0.f, 0.f, 0.f, 0.f, 0.f, 0.f};
    int lim = min(128, NN - base);
    for (int ni = 0; ni < lim; ni++) {
        float hv = g_h[(size_t)(base + ni) * FF + t];
#pragma unroll
        for (int r = 0; r < RR; r++) acc[r] += wc[r][ni] * hv;
    }
#pragma unroll
    for (int r = 0; r < RR; r++) atomicAdd(&g_s[r * FF + t], acc[r]);
}

__global__ void k_final(const float* __restrict__ W2, const float* __restrict__ b2,
                        const float* __restrict__ Wc, const float* __restrict__ bc,
                        float* __restrict__ out) {
    __shared__ float g[FF];
    int f = threadIdx.x;
    float acc = 0.f;
    for (int rk = 0; rk < RR * FF; rk++)
        acc += g_s[rk] * W2[(size_t)rk * FF + f];
    float gb = 0.f;
#pragma unroll
    for (int r = 0; r < RR; r++) gb += b2[r * FF + f];
    g[f] = acc * (1.f / NN) + gb;
    __syncthreads();
    if (f < 2) {
        float o = bc[f];
        for (int k = 0; k < FF; k++) o += g[k] * Wc[k * 2 + f];
        out[f] = o;
    }
}

// ---------------- launch ----------------
extern "C" void kernel_launch(void* const* d_in, const int* in_sizes, int n_in,
                              void* d_out, int out_size) {
    const float* x    = (const float*)d_in[0];
    const int*   esrc = (const int*)  d_in[1];
    const int*   edst = (const int*)  d_in[2];
    const float* W1   = (const float*)d_in[3];
    const float* b1   = (const float*)d_in[4];
    const float* W2   = (const float*)d_in[5];
    const float* b2   = (const float*)d_in[6];
    const float* Wc   = (const float*)d_in[7];
    const float* bc   = (const float*)d_in[8];
    float* out = (float*)d_out;

    void *p_do, *p_di, *p_cur, *p_c, *p_s;
    cudaGetSymbolAddress(&p_do,  g_deg_out);
    cudaGetSymbolAddress(&p_di,  g_deg_in);
    cudaGetSymbolAddress(&p_cur, g_cursor2);
    cudaGetSymbolAddress(&p_c,   g_c);
    cudaGetSymbolAddress(&p_s,   g_s);

    // ---- fork: side stream runs the dense (tensor-pipe) chain ----
    cudaEventRecord(g_evF, 0);
    cudaStreamWaitEvent(g_s2, g_evF, 0);

    k_prepX<<<(NN * FF / 4 + 255) / 256, 256, 0, g_s2>>>(x);
    k_prepB<<<(RR * FF * FF + 255) / 256, 256, 0, g_s2>>>(W1);
    k_bsum1<<<1, FF, 0, g_s2>>>(b1);
    k_gemmZ<<<dim3(782, 6), 256, 0, g_s2>>>();
    cudaEventRecord(g_evJ, g_s2);

    // ---- main stream: graph prep (L2-atomic-bound) ----
    cudaMemsetAsync(p_do,  0, (size_t)RN * 4, 0);
    cudaMemsetAsync(p_di,  0, (size_t)RN * 4, 0);
    cudaMemsetAsync(p_cur, 0, (size_t)NN * 4, 0);
    cudaMemsetAsync(p_c,   0, (size_t)RN * 4, 0);
    cudaMemsetAsync(p_s,   0, (size_t)RR * FF * 4, 0);

    k_deg  <<<(RE + 255) / 256, 256>>>(esrc, edst);
    k_norm <<<(RN + 255) / 256, 256>>>();
    k_deg2 <<<(NN + 255) / 256, 256>>>();
    k_dscan1<<<NB2, 1024>>>();
    k_dscan2<<<1, 128>>>();
    k_dscan3<<<NB2, 1024>>>();
    k_fill2<<<(RE + 255) / 256, 256>>>(esrc, edst);

    // ---- join: aggregation needs both Z (s2) and the CSR (main) ----
    cudaStreamWaitEvent(0, g_evJ, 0);
    k_agg2 <<<(NN * 32 + 255) / 256, 256>>>();
    k_reduce<<<(NN + 127) / 128, 128>>>();
    k_final<<<1, FF>>>(W2, b2, Wc, bc, out);
}